// round 16
// baseline (speedup 1.0000x reference)
#include <cuda_runtime.h>
#include <cuda_fp16.h>
#include <math.h>
#include <stdint.h>

#define BS 16
#define NCLS 80
#define NKPT 51
#define A_TOT 8400
#define MAX_DET 100
#define CONF 0.25f

// output layout (floats)
#define O_NUM   0
#define O_BOX   16
#define O_SCORE 6416
#define O_CLS   8016
#define O_KPT   9616

// device scratch
__device__ __align__(16) __half g_wh[229376];   // [s][n=256][k], hi part
__device__ __align__(16) __half g_wl[229376];   // lo part
__device__ float g_bias[3 * 256];
__device__ float g_dbox[(size_t)BS * 4 * A_TOT];
__device__ float g_kpts[(size_t)BS * NKPT * A_TOT];
__device__ float g_maxs[BS * A_TOT];
__device__ int   g_cls[BS * A_TOT];

// ---------------------------------------------------------------------------
// Pack (single launch, vectorized x4): split weights into fp16 hi/lo + bias.
// ---------------------------------------------------------------------------
__global__ void pack_k(const float* __restrict__ w20, const float* __restrict__ b20,
                       const float* __restrict__ w21, const float* __restrict__ b21,
                       const float* __restrict__ w22, const float* __restrict__ b22,
                       const float* __restrict__ w30, const float* __restrict__ b30,
                       const float* __restrict__ w31, const float* __restrict__ b31,
                       const float* __restrict__ w32, const float* __restrict__ b32,
                       const float* __restrict__ w40, const float* __restrict__ b40,
                       const float* __restrict__ w41, const float* __restrict__ b41,
                       const float* __restrict__ w42, const float* __restrict__ b42)
{
    int g4 = blockIdx.x * blockDim.x + threadIdx.x;
    if (g4 >= 57344) return;                     // 229376 / 4
    int s, idx4, C;
    if (g4 < 8192)       { s = 0; idx4 = g4;         C = 128; }
    else if (g4 < 24576) { s = 1; idx4 = g4 - 8192;  C = 256; }
    else                 { s = 2; idx4 = g4 - 24576; C = 512; }
    const float* w2 = (s == 0) ? w20 : (s == 1) ? w21 : w22;
    const float* b2 = (s == 0) ? b20 : (s == 1) ? b21 : b22;
    const float* w3 = (s == 0) ? w30 : (s == 1) ? w31 : w32;
    const float* b3 = (s == 0) ? b30 : (s == 1) ? b31 : b32;
    const float* w4 = (s == 0) ? w40 : (s == 1) ? w41 : w42;
    const float* b4 = (s == 0) ? b40 : (s == 1) ? b41 : b42;

    const int idx = idx4 * 4;
    const int n = idx / C;
    const int k = idx - n * C;

    float4 v = make_float4(0.f, 0.f, 0.f, 0.f);
    if (n < 64)        v = *(const float4*)&w2[n * C + k];
    else if (n < 144)  v = *(const float4*)&w3[(n - 64) * C + k];
    else if (n < 195)  v = *(const float4*)&w4[(n - 144) * C + k];

    float va[4] = {v.x, v.y, v.z, v.w};
    __half hh[4], ll[4];
#pragma unroll
    for (int j = 0; j < 4; j++) {
        hh[j] = __float2half_rn(va[j]);
        ll[j] = __float2half_rn(va[j] - __half2float(hh[j]));
    }
    *(uint2*)&g_wh[g4 * 4] = *(uint2*)hh;
    *(uint2*)&g_wl[g4 * 4] = *(uint2*)ll;

    if (k == 0) {
        float bb = 0.f;
        if (n < 64)        bb = b2[n];
        else if (n < 144)  bb = b3[n - 64];
        else if (n < 195)  bb = b4[n - 144];
        g_bias[s * 256 + n] = bb;
    }
}

// ---------------------------------------------------------------------------
__device__ __forceinline__ void mma_f16(float* c, const uint32_t* a,
                                        uint32_t b0, uint32_t b1)
{
    asm volatile(
        "mma.sync.aligned.m16n8k16.row.col.f32.f16.f16.f32 "
        "{%0,%1,%2,%3}, {%4,%5,%6,%7}, {%8,%9}, {%0,%1,%2,%3};"
        : "+f"(c[0]), "+f"(c[1]), "+f"(c[2]), "+f"(c[3])
        : "r"(a[0]), "r"(a[1]), "r"(a[2]), "r"(a[3]), "r"(b0), "r"(b1));
}

__device__ __forceinline__ void ldm_x4(uint32_t* r, uint32_t addr)
{
    asm volatile("ldmatrix.sync.aligned.m8n8.x4.shared.b16 {%0,%1,%2,%3}, [%4];"
                 : "=r"(r[0]), "=r"(r[1]), "=r"(r[2]), "=r"(r[3]) : "r"(addr));
}

__device__ __forceinline__ void ldm_x2(uint32_t* r, uint32_t addr)
{
    asm volatile("ldmatrix.sync.aligned.m8n8.x2.shared.b16 {%0,%1}, [%2];"
                 : "=r"(r[0]), "=r"(r[1]) : "r"(addr));
}

// split into (hi, fp16-exact via mantissa mask) + (lo fp16), packed converts
__device__ __forceinline__ void split2(float v0, float v1, uint32_t& hh, uint32_t& ll)
{
    float h0 = __uint_as_float(__float_as_uint(v0) & 0xFFFFE000u);
    float h1 = __uint_as_float(__float_as_uint(v1) & 0xFFFFE000u);
    __half2 hp = __float22half2_rn(make_float2(h0, h1));
    __half2 lp = __float22half2_rn(make_float2(v0 - h0, v1 - h1));
    hh = *(uint32_t*)&hp;
    ll = *(uint32_t*)&lp;
}

__device__ __forceinline__ float dfl16(const float* v) {
    float mx = v[0];
#pragma unroll
    for (int i = 1; i < 16; i++) mx = fmaxf(mx, v[i]);
    float s = 0.f, w = 0.f;
#pragma unroll
    for (int i = 0; i < 16; i++) {
        float e = expf(v[i] - mx);
        s += e;
        w += e * (float)i;
    }
    return w / s;
}

// smem word layout, K-chunk 32, row stride 20 words (40 halves, 80B).
// per stage: A_HI 64x20=1280 | A_LO 1280 | B_HI 200x20=4000 | B_LO 4000 -> 10560
// D tile (64 x 201 fp32 = 12864 words) aliases the two stages after mainloop.
#define ST_WORDS 10560
#define A_LO_W   1280
#define B_HI_W   2560
#define B_LO_W   6560
#define SM_D     0
#define SM_BIAS  21120
#define SM_WORDS 21376
#define SMEM_BYTES (SM_WORDS * 4)      // 85504

// ---------------------------------------------------------------------------
// Fused GEMM (split-fp16 mma.sync, ldmatrix, 2-stage cp.async.cg) + decode.
// R13 mainloop + A-LDG prefetch hoisted above the pipeline wait (isolated
// retest of the one untested R11 component).
// M=64 anchors x N=200 outs per CTA, 256 threads = 8 warps, 2 CTAs/SM.
// wm=wid&1 (m32), wn=wid>>1. n8-tile counts per wn: {6,7,6,6}
// (col offsets {0,48,104,152}); wn1's odd 7th tile = cols 96..103 via ldm.x2.
// CTA order: s2 (16 chunks) first, then s1, then s0 (longest-first).
// ---------------------------------------------------------------------------
__global__ void __launch_bounds__(256, 2) gemm_tc(const float* __restrict__ x0,
                                                  const float* __restrict__ x1,
                                                  const float* __restrict__ x2)
{
    extern __shared__ uint32_t sm[];
    float* smf = (float*)sm;

    int bid = blockIdx.x;
    int s, rel;
    if (bid < 112)      { s = 2; rel = bid; }
    else if (bid < 512) { s = 1; rel = bid - 112; }
    else                { s = 0; rel = bid - 512; }
    const int tpbA[3]  = {100, 25, 7};
    const int CsA[3]   = {128, 256, 512};
    const int HWA[3]   = {6400, 1600, 400};
    const int soffA[3] = {0, 6400, 8000};
    const int WA[3]    = {80, 40, 20};
    const int woffA[3] = {0, 32768, 98304};
    const float strA[3] = {8.f, 16.f, 32.f};

    const int C = CsA[s], HW = HWA[s], W = WA[s];
    const float stride = strA[s];
    const int b    = rel / tpbA[s];
    const int tile = rel - b * tpbA[s];
    const int pos0 = tile * 64;
    const int valid = min(64, HW - pos0);

    const float* xsel = (s == 0) ? x0 : (s == 1) ? x1 : x2;
    const float* xb = xsel + (size_t)b * C * HW + pos0;
    const __half* wh = g_wh + woffA[s];
    const __half* wl = g_wl + woffA[s];

    const int t = threadIdx.x;
    const int lane = t & 31;
    const int wid = t >> 5;
    const int wm = wid & 1;
    const int wn = wid >> 1;
    const int ncol0 = (wn == 0) ? 0 : (wn == 1) ? 48 : (wn == 2) ? 104 : 152;
    const bool xtra = (wn == 1);          // extra n8 tile at cols 96..103

    const uint32_t smb = (uint32_t)__cvta_generic_to_shared(sm);

    smf[SM_BIAS + t] = g_bias[s * 256 + t];

    float acc0[6][4];   // mt=0, index ntp*2+h (3 n16 pairs)
    float acc1[6][4];   // mt=1
    float accx0[4], accx1[4];   // extra n8 tile (wn1)
#pragma unroll
    for (int i = 0; i < 6; i++)
#pragma unroll
        for (int j = 0; j < 4; j++) { acc0[i][j] = 0.f; acc1[i][j] = 0.f; }
#pragma unroll
    for (int j = 0; j < 4; j++) { accx0[j] = 0.f; accx1[j] = 0.f; }

    const int am   = t & 63;
    const int akp0 = t >> 6;
    const int bn   = t >> 2;
    const int boff = t & 3;

    const int nkt = C >> 5;

    // ---- prologue: chunk 0 ----
    {
#pragma unroll
        for (int i = 0; i < 4; i++) {
            const int n = bn + i * 64;
            if (n < 200) {
                const uint32_t dsth = smb + (B_HI_W + n * 20 + boff * 4) * 4;
                const uint32_t dstl = smb + (B_LO_W + n * 20 + boff * 4) * 4;
                asm volatile("cp.async.cg.shared.global [%0], [%1], 16;"
                             :: "r"(dsth), "l"(wh + (size_t)n * C + boff * 8) : "memory");
                asm volatile("cp.async.cg.shared.global [%0], [%1], 16;"
                             :: "r"(dstl), "l"(wl + (size_t)n * C + boff * 8) : "memory");
            }
        }
        asm volatile("cp.async.commit_group;" ::: "memory");
        float v[8];
#pragma unroll
        for (int j = 0; j < 8; j++)
            v[j] = (am < valid) ? xb[(size_t)(akp0 * 8 + j) * HW + am] : 0.f;
        uint32_t hw4[4], lw4[4];
#pragma unroll
        for (int p = 0; p < 4; p++) split2(v[2*p], v[2*p+1], hw4[p], lw4[p]);
        *(uint4*)&sm[am * 20 + akp0 * 4]          = *(uint4*)hw4;
        *(uint4*)&sm[A_LO_W + am * 20 + akp0 * 4] = *(uint4*)lw4;
    }

    for (int kt = 0; kt < nkt; kt++) {
        const int st = (kt & 1) ? ST_WORDS : 0;
        const bool pf = (kt + 1 < nkt);
        const int stn = ((kt + 1) & 1) ? ST_WORDS : 0;

        // A register prefetch for kt+1 — BEFORE the wait (smem-independent),
        // overlapping global latency with the pipeline wait + barrier.
        float apre[8];
        if (pf) {
            const int c1 = (kt + 1) << 5;
#pragma unroll
            for (int j = 0; j < 8; j++)
                apre[j] = (am < valid) ? xb[(size_t)(c1 + akp0 * 8 + j) * HW + am] : 0.f;
        }

        asm volatile("cp.async.wait_group 0;" ::: "memory");
        __syncthreads();

        // issue B cp.async for kt+1 into the other stage (must be post-barrier)
        if (pf) {
            const int c1 = (kt + 1) << 5;
#pragma unroll
            for (int i = 0; i < 4; i++) {
                const int n = bn + i * 64;
                if (n < 200) {
                    const uint32_t dsth = smb + (stn + B_HI_W + n * 20 + boff * 4) * 4;
                    const uint32_t dstl = smb + (stn + B_LO_W + n * 20 + boff * 4) * 4;
                    asm volatile("cp.async.cg.shared.global [%0], [%1], 16;"
                                 :: "r"(dsth), "l"(wh + (size_t)n * C + c1 + boff * 8) : "memory");
                    asm volatile("cp.async.cg.shared.global [%0], [%1], 16;"
                                 :: "r"(dstl), "l"(wl + (size_t)n * C + c1 + boff * 8) : "memory");
                }
            }
            asm volatile("cp.async.commit_group;" ::: "memory");
        }

        // ---- compute current chunk ----
#pragma unroll
        for (int k16 = 0; k16 < 2; k16++) {
            uint32_t ah[2][4], al[2][4];
            const uint32_t acol = k16 * 32 + (lane >> 4) * 16;
#pragma unroll
            for (int mt = 0; mt < 2; mt++) {
                const int row = wm * 32 + mt * 16 + (lane & 15);
                const uint32_t ba = smb + (st + row * 20) * 4 + acol;
                ldm_x4(ah[mt], ba);
                ldm_x4(al[mt], ba + A_LO_W * 4);
            }
            const int brow = (lane & 7) + ((lane >> 4) << 3);
            const uint32_t bcol = ((lane >> 3) & 1) * 16 + k16 * 32;
#pragma unroll
            for (int ntp = 0; ntp < 3; ntp++) {
                const int nb = ncol0 + ntp * 16 + brow;
                uint32_t bh[4], bl[4];
                const uint32_t bbp = smb + (st + B_HI_W + nb * 20) * 4 + bcol;
                ldm_x4(bh, bbp);
                ldm_x4(bl, bbp + (B_LO_W - B_HI_W) * 4);
#pragma unroll
                for (int h = 0; h < 2; h++) {
                    const int g = ntp * 2 + h;
                    mma_f16(acc0[g], ah[0], bh[2*h], bh[2*h+1]);
                    mma_f16(acc0[g], ah[0], bl[2*h], bl[2*h+1]);
                    mma_f16(acc0[g], al[0], bh[2*h], bh[2*h+1]);
                    mma_f16(acc1[g], ah[1], bh[2*h], bh[2*h+1]);
                    mma_f16(acc1[g], ah[1], bl[2*h], bl[2*h+1]);
                    mma_f16(acc1[g], al[1], bh[2*h], bh[2*h+1]);
                }
            }
            if (xtra) {
                const int xrow = 96 + (lane & 7);
                const uint32_t xoff = ((lane >> 3) & 1) * 16 + k16 * 32;
                uint32_t bh2[2], bl2[2];
                const uint32_t xba = smb + (st + B_HI_W + xrow * 20) * 4 + xoff;
                ldm_x2(bh2, xba);
                ldm_x2(bl2, xba + (B_LO_W - B_HI_W) * 4);
                mma_f16(accx0, ah[0], bh2[0], bh2[1]);
                mma_f16(accx0, ah[0], bl2[0], bl2[1]);
                mma_f16(accx0, al[0], bh2[0], bh2[1]);
                mma_f16(accx1, ah[1], bh2[0], bh2[1]);
                mma_f16(accx1, ah[1], bl2[0], bl2[1]);
                mma_f16(accx1, al[1], bh2[0], bh2[1]);
            }
        }

        if (pf) {
            uint32_t hw4[4], lw4[4];
#pragma unroll
            for (int p = 0; p < 4; p++) split2(apre[2*p], apre[2*p+1], hw4[p], lw4[p]);
            *(uint4*)&sm[stn + am * 20 + akp0 * 4]          = *(uint4*)hw4;
            *(uint4*)&sm[stn + A_LO_W + am * 20 + akp0 * 4] = *(uint4*)lw4;
        }
    }
    __syncthreads();   // mainloop done; stage smem reused as D tile

    // ---- stage D tile (cols 0..199, stride 201) ----
#pragma unroll
    for (int ntp = 0; ntp < 3; ntp++) {
#pragma unroll
        for (int h = 0; h < 2; h++) {
            const int n = ncol0 + ntp * 16 + h * 8 + (lane & 3) * 2;
            const int g = ntp * 2 + h;
#pragma unroll
            for (int mt = 0; mt < 2; mt++) {
                const int r = wm * 32 + mt * 16 + (lane >> 2);
                const float* c = (mt == 0) ? acc0[g] : acc1[g];
                smf[SM_D + r * 201 + n]           = c[0];
                smf[SM_D + r * 201 + n + 1]       = c[1];
                smf[SM_D + (r + 8) * 201 + n]     = c[2];
                smf[SM_D + (r + 8) * 201 + n + 1] = c[3];
            }
        }
    }
    if (xtra) {
        const int n = 96 + (lane & 3) * 2;
#pragma unroll
        for (int mt = 0; mt < 2; mt++) {
            const int r = wm * 32 + mt * 16 + (lane >> 2);
            const float* c = (mt == 0) ? accx0 : accx1;
            smf[SM_D + r * 201 + n]           = c[0];
            smf[SM_D + r * 201 + n + 1]       = c[1];
            smf[SM_D + (r + 8) * 201 + n]     = c[2];
            smf[SM_D + (r + 8) * 201 + n + 1] = c[3];
        }
    }
    __syncthreads();

    // ---- decode epilogue: 4 threads per anchor (64 x 4 = 256) ----
    {
        const int ar  = t >> 2;
        const int sub = t & 3;
        const bool ok = ar < valid;
        const int pos = pos0 + ar;
        const int a_g = soffA[s] + pos;
        const int py = pos / W, px = pos - py * W;
        const float gx = px + 0.5f, gy = py + 0.5f;
        const float* Dr = smf + SM_D + ar * 201;
        const float* bi = smf + SM_BIAS;
        const unsigned msk = 0xffffffffu;

        float v16[16];
#pragma unroll
        for (int i = 0; i < 16; i++) v16[i] = Dr[sub * 16 + i] + bi[sub * 16 + i];
        float d = dfl16(v16);
        const float d0 = __shfl_sync(msk, d, 0, 4);
        const float d1 = __shfl_sync(msk, d, 1, 4);
        const float d2 = __shfl_sync(msk, d, 2, 4);
        const float d3 = __shfl_sync(msk, d, 3, 4);
        if (ok && sub == 0) {
            float x1 = gx - d0, y1 = gy - d1;
            float x2 = gx + d2, y2 = gy + d3;
            g_dbox[((size_t)b * 4 + 0) * A_TOT + a_g] = (x1 + x2) * 0.5f * stride;
            g_dbox[((size_t)b * 4 + 1) * A_TOT + a_g] = (y1 + y2) * 0.5f * stride;
            g_dbox[((size_t)b * 4 + 2) * A_TOT + a_g] = (x2 - x1) * stride;
            g_dbox[((size_t)b * 4 + 3) * A_TOT + a_g] = (y2 - y1) * stride;
        }

        float best = -INFINITY; int bcls = 0;
#pragma unroll
        for (int c = 0; c < 20; c++) {
            const int cc = sub * 20 + c;
            float v = Dr[64 + cc] + bi[64 + cc];
            if (v > best) { best = v; bcls = cc; }
        }
#pragma unroll
        for (int o = 2; o > 0; o >>= 1) {
            float v2 = __shfl_down_sync(msk, best, o, 4);
            int   i2 = __shfl_down_sync(msk, bcls, o, 4);
            if (v2 > best || (v2 == best && i2 < bcls)) { best = v2; bcls = i2; }
        }
        if (ok && sub == 0) {
            g_maxs[b * A_TOT + a_g] = 1.f / (1.f + expf(-best));
            g_cls[b * A_TOT + a_g]  = bcls;
        }

        if (ok) {
            for (int nk = sub; nk < NKPT; nk += 4) {
                float v = Dr[144 + nk] + bi[144 + nk];
                const int comp = nk % 3;
                float o = (comp == 0) ? (v * 2.f + (gx - 0.5f)) * stride
                        : (comp == 1) ? (v * 2.f + (gy - 0.5f)) * stride
                                      : 1.f / (1.f + expf(-v));
                g_kpts[((size_t)b * NKPT + nk) * A_TOT + a_g] = o;
            }
        }
    }
}

// ---------------------------------------------------------------------------
// Per-batch top-100 via histogram threshold + bitonic sort of candidates.
// ---------------------------------------------------------------------------
#define NBIN 4096
#define CANDC 1024

__global__ void __launch_bounds__(1024) topk_k(float* __restrict__ out)
{
    __shared__ int hist[NBIN];
    __shared__ int coarse[256];
    __shared__ unsigned long long cand[CANDC];
    __shared__ int s_cnt, s_T;
    __shared__ int s_idx[MAX_DET];
    __shared__ float s_val[MAX_DET];

    const int b = blockIdx.x;
    const int t = threadIdx.x;
    const float* scores = g_maxs + b * A_TOT;

#pragma unroll
    for (int i = 0; i < NBIN / 1024; i++) hist[t + i * 1024] = 0;
    if (t < CANDC) cand[t] = 0ull;
    if (t == 0) s_cnt = 0;
    __syncthreads();

    for (int i = t; i < A_TOT; i += 1024) {
        int bin = min(NBIN - 1, max(0, (int)(scores[i] * (float)NBIN)));
        atomicAdd(&hist[bin], 1);
    }
    __syncthreads();

    if (t < 256) {
        int sum = 0;
#pragma unroll
        for (int i = 0; i < 16; i++) sum += hist[t * 16 + i];
        coarse[t] = sum;
    }
    __syncthreads();

    if (t == 0) {
        int acc = 0, T = 0;
        int c;
        for (c = 255; c >= 0; c--) {
            if (acc + coarse[c] >= MAX_DET) break;
            acc += coarse[c];
        }
        if (c < 0) { T = 0; }
        else {
            for (int bin = c * 16 + 15; bin >= c * 16; bin--) {
                acc += hist[bin];
                if (acc >= MAX_DET) { T = bin; break; }
                if (bin == c * 16) T = bin;
            }
        }
        s_T = T;
    }
    __syncthreads();

    const int T = s_T;
    for (int i = t; i < A_TOT; i += 1024) {
        float v = scores[i];
        int bin = min(NBIN - 1, max(0, (int)(v * (float)NBIN)));
        if (bin >= T) {
            int pos = atomicAdd(&s_cnt, 1);
            if (pos < CANDC)
                cand[pos] = ((unsigned long long)__float_as_uint(v) << 32)
                          | (unsigned long long)(A_TOT - 1 - i);
        }
    }
    __syncthreads();

    for (int k = 2; k <= CANDC; k <<= 1) {
        for (int j = k >> 1; j > 0; j >>= 1) {
            if (t < CANDC / 2) {
                int idx = ((t & ~(j - 1)) << 1) | (t & (j - 1));
                int ixj = idx | j;
                unsigned long long a = cand[idx], bb2 = cand[ixj];
                bool descBlk = ((idx & k) == 0);
                if ((a < bb2) == descBlk) { cand[idx] = bb2; cand[ixj] = a; }
            }
            __syncthreads();
        }
    }

    if (t < MAX_DET) {
        unsigned long long key = cand[t];
        s_val[t] = __uint_as_float((uint32_t)(key >> 32));
        s_idx[t] = A_TOT - 1 - (int)(key & 0xFFFFFFFFull);
    }
    __syncthreads();

    if (t == 0) {
        int cnt = 0;
        for (int j = 0; j < MAX_DET; j++) cnt += (s_val[j] > CONF) ? 1 : 0;
        out[O_NUM + b] = (float)cnt;
    }
    for (int e = t; e < MAX_DET * 4; e += 1024) {
        int j = e >> 2, c = e & 3;
        out[O_BOX + ((size_t)b * MAX_DET + j) * 4 + c] =
            g_dbox[((size_t)b * 4 + c) * A_TOT + s_idx[j]];
    }
    for (int j = t; j < MAX_DET; j += 1024) {
        out[O_SCORE + b * MAX_DET + j] = s_val[j];
        out[O_CLS   + b * MAX_DET + j] = (float)g_cls[b * A_TOT + s_idx[j]];
    }
    for (int e = t; e < MAX_DET * NKPT; e += 1024) {
        int j = e / NKPT, nk = e - j * NKPT;
        out[O_KPT + ((size_t)b * MAX_DET + j) * NKPT + nk] =
            g_kpts[((size_t)b * NKPT + nk) * A_TOT + s_idx[j]];
    }
}

// ---------------------------------------------------------------------------
extern "C" void kernel_launch(void* const* d_in, const int* in_sizes, int n_in,
                              void* d_out, int out_size)
{
    cudaFuncSetAttribute(gemm_tc, cudaFuncAttributeMaxDynamicSharedMemorySize, SMEM_BYTES);

    pack_k<<<(57344 + 255) / 256, 256>>>(
        (const float*)d_in[3],  (const float*)d_in[4],
        (const float*)d_in[5],  (const float*)d_in[6],
        (const float*)d_in[7],  (const float*)d_in[8],
        (const float*)d_in[9],  (const float*)d_in[10],
        (const float*)d_in[11], (const float*)d_in[12],
        (const float*)d_in[13], (const float*)d_in[14],
        (const float*)d_in[15], (const float*)d_in[16],
        (const float*)d_in[17], (const float*)d_in[18],
        (const float*)d_in[19], (const float*)d_in[20]);

    gemm_tc<<<2112, 256, SMEM_BYTES>>>((const float*)d_in[0],
                                       (const float*)d_in[1],
                                       (const float*)d_in[2]);

    topk_k<<<BS, 1024>>>((float*)d_out);
}

// round 17
// speedup vs baseline: 1.0543x; 1.0543x over previous
#include <cuda_runtime.h>
#include <cuda_fp16.h>
#include <math.h>
#include <stdint.h>

#define BS 16
#define NCLS 80
#define NKPT 51
#define A_TOT 8400
#define MAX_DET 100
#define CONF 0.25f

// output layout (floats)
#define O_NUM   0
#define O_BOX   16
#define O_SCORE 6416
#define O_CLS   8016
#define O_KPT   9616

// device scratch
__device__ __align__(16) __half g_wh[229376];   // [s][n=256][k], hi part
__device__ __align__(16) __half g_wl[229376];   // lo part
__device__ float g_bias[3 * 256];
__device__ float g_dbox[(size_t)BS * 4 * A_TOT];
__device__ float g_kpts[(size_t)BS * NKPT * A_TOT];
__device__ float g_maxs[BS * A_TOT];
__device__ int   g_cls[BS * A_TOT];

// ---------------------------------------------------------------------------
// Pack (single launch, vectorized x4): split weights into fp16 hi/lo + bias.
// ---------------------------------------------------------------------------
__global__ void pack_k(const float* __restrict__ w20, const float* __restrict__ b20,
                       const float* __restrict__ w21, const float* __restrict__ b21,
                       const float* __restrict__ w22, const float* __restrict__ b22,
                       const float* __restrict__ w30, const float* __restrict__ b30,
                       const float* __restrict__ w31, const float* __restrict__ b31,
                       const float* __restrict__ w32, const float* __restrict__ b32,
                       const float* __restrict__ w40, const float* __restrict__ b40,
                       const float* __restrict__ w41, const float* __restrict__ b41,
                       const float* __restrict__ w42, const float* __restrict__ b42)
{
    int g4 = blockIdx.x * blockDim.x + threadIdx.x;
    if (g4 >= 57344) return;                     // 229376 / 4
    int s, idx4, C;
    if (g4 < 8192)       { s = 0; idx4 = g4;         C = 128; }
    else if (g4 < 24576) { s = 1; idx4 = g4 - 8192;  C = 256; }
    else                 { s = 2; idx4 = g4 - 24576; C = 512; }
    const float* w2 = (s == 0) ? w20 : (s == 1) ? w21 : w22;
    const float* b2 = (s == 0) ? b20 : (s == 1) ? b21 : b22;
    const float* w3 = (s == 0) ? w30 : (s == 1) ? w31 : w32;
    const float* b3 = (s == 0) ? b30 : (s == 1) ? b31 : b32;
    const float* w4 = (s == 0) ? w40 : (s == 1) ? w41 : w42;
    const float* b4 = (s == 0) ? b40 : (s == 1) ? b41 : b42;

    const int idx = idx4 * 4;
    const int n = idx / C;
    const int k = idx - n * C;

    float4 v = make_float4(0.f, 0.f, 0.f, 0.f);
    if (n < 64)        v = *(const float4*)&w2[n * C + k];
    else if (n < 144)  v = *(const float4*)&w3[(n - 64) * C + k];
    else if (n < 195)  v = *(const float4*)&w4[(n - 144) * C + k];

    float va[4] = {v.x, v.y, v.z, v.w};
    __half hh[4], ll[4];
#pragma unroll
    for (int j = 0; j < 4; j++) {
        hh[j] = __float2half_rn(va[j]);
        ll[j] = __float2half_rn(va[j] - __half2float(hh[j]));
    }
    *(uint2*)&g_wh[g4 * 4] = *(uint2*)hh;
    *(uint2*)&g_wl[g4 * 4] = *(uint2*)ll;

    if (k == 0) {
        float bb = 0.f;
        if (n < 64)        bb = b2[n];
        else if (n < 144)  bb = b3[n - 64];
        else if (n < 195)  bb = b4[n - 144];
        g_bias[s * 256 + n] = bb;
    }
}

// ---------------------------------------------------------------------------
__device__ __forceinline__ void mma_f16(float* c, const uint32_t* a,
                                        uint32_t b0, uint32_t b1)
{
    asm volatile(
        "mma.sync.aligned.m16n8k16.row.col.f32.f16.f16.f32 "
        "{%0,%1,%2,%3}, {%4,%5,%6,%7}, {%8,%9}, {%0,%1,%2,%3};"
        : "+f"(c[0]), "+f"(c[1]), "+f"(c[2]), "+f"(c[3])
        : "r"(a[0]), "r"(a[1]), "r"(a[2]), "r"(a[3]), "r"(b0), "r"(b1));
}

__device__ __forceinline__ void ldm_x4(uint32_t* r, uint32_t addr)
{
    asm volatile("ldmatrix.sync.aligned.m8n8.x4.shared.b16 {%0,%1,%2,%3}, [%4];"
                 : "=r"(r[0]), "=r"(r[1]), "=r"(r[2]), "=r"(r[3]) : "r"(addr));
}

__device__ __forceinline__ void ldm_x2(uint32_t* r, uint32_t addr)
{
    asm volatile("ldmatrix.sync.aligned.m8n8.x2.shared.b16 {%0,%1}, [%2];"
                 : "=r"(r[0]), "=r"(r[1]) : "r"(addr));
}

// split into (hi, fp16-exact via mantissa mask) + (lo fp16), packed converts
__device__ __forceinline__ void split2(float v0, float v1, uint32_t& hh, uint32_t& ll)
{
    float h0 = __uint_as_float(__float_as_uint(v0) & 0xFFFFE000u);
    float h1 = __uint_as_float(__float_as_uint(v1) & 0xFFFFE000u);
    __half2 hp = __float22half2_rn(make_float2(h0, h1));
    __half2 lp = __float22half2_rn(make_float2(v0 - h0, v1 - h1));
    hh = *(uint32_t*)&hp;
    ll = *(uint32_t*)&lp;
}

__device__ __forceinline__ float dfl16(const float* v) {
    float mx = v[0];
#pragma unroll
    for (int i = 1; i < 16; i++) mx = fmaxf(mx, v[i]);
    float s = 0.f, w = 0.f;
#pragma unroll
    for (int i = 0; i < 16; i++) {
        float e = expf(v[i] - mx);
        s += e;
        w += e * (float)i;
    }
    return w / s;
}

// smem word layout, K-chunk 32, row stride 20 words (40 halves, 80B).
// per stage: A_HI 64x20=1280 | A_LO 1280 | B_HI 200x20=4000 | B_LO 4000 -> 10560
// D tile (64 x 201 fp32 = 12864 words) aliases the two stages after mainloop.
#define ST_WORDS 10560
#define A_LO_W   1280
#define B_HI_W   2560
#define B_LO_W   6560
#define SM_D     0
#define SM_BIAS  21120
#define SM_WORDS 21376
#define SMEM_BYTES (SM_WORDS * 4)      // 85504

// ---------------------------------------------------------------------------
// Fused GEMM (split-fp16 mma.sync, ldmatrix, 2-stage cp.async.cg) + decode.
// Best-known configuration (R13 mainloop exactly; A-prefetch post-barrier).
// M=64 anchors x N=200 outs per CTA, 256 threads = 8 warps, 2 CTAs/SM.
// wm=wid&1 (m32), wn=wid>>1. n8-tile counts per wn: {6,7,6,6}
// (col offsets {0,48,104,152}); wn1's odd 7th tile = cols 96..103 via ldm.x2.
// CTA order: s2 (16 chunks) first, then s1, then s0 (longest-first).
// ---------------------------------------------------------------------------
__global__ void __launch_bounds__(256, 2) gemm_tc(const float* __restrict__ x0,
                                                  const float* __restrict__ x1,
                                                  const float* __restrict__ x2)
{
    extern __shared__ uint32_t sm[];
    float* smf = (float*)sm;

    int bid = blockIdx.x;
    int s, rel;
    if (bid < 112)      { s = 2; rel = bid; }
    else if (bid < 512) { s = 1; rel = bid - 112; }
    else                { s = 0; rel = bid - 512; }
    const int tpbA[3]  = {100, 25, 7};
    const int CsA[3]   = {128, 256, 512};
    const int HWA[3]   = {6400, 1600, 400};
    const int soffA[3] = {0, 6400, 8000};
    const int WA[3]    = {80, 40, 20};
    const int woffA[3] = {0, 32768, 98304};
    const float strA[3] = {8.f, 16.f, 32.f};

    const int C = CsA[s], HW = HWA[s], W = WA[s];
    const float stride = strA[s];
    const int b    = rel / tpbA[s];
    const int tile = rel - b * tpbA[s];
    const int pos0 = tile * 64;
    const int valid = min(64, HW - pos0);

    const float* xsel = (s == 0) ? x0 : (s == 1) ? x1 : x2;
    const float* xb = xsel + (size_t)b * C * HW + pos0;
    const __half* wh = g_wh + woffA[s];
    const __half* wl = g_wl + woffA[s];

    const int t = threadIdx.x;
    const int lane = t & 31;
    const int wid = t >> 5;
    const int wm = wid & 1;
    const int wn = wid >> 1;
    const int ncol0 = (wn == 0) ? 0 : (wn == 1) ? 48 : (wn == 2) ? 104 : 152;
    const bool xtra = (wn == 1);          // extra n8 tile at cols 96..103

    const uint32_t smb = (uint32_t)__cvta_generic_to_shared(sm);

    smf[SM_BIAS + t] = g_bias[s * 256 + t];

    float acc0[6][4];   // mt=0, index ntp*2+h (3 n16 pairs)
    float acc1[6][4];   // mt=1
    float accx0[4], accx1[4];   // extra n8 tile (wn1)
#pragma unroll
    for (int i = 0; i < 6; i++)
#pragma unroll
        for (int j = 0; j < 4; j++) { acc0[i][j] = 0.f; acc1[i][j] = 0.f; }
#pragma unroll
    for (int j = 0; j < 4; j++) { accx0[j] = 0.f; accx1[j] = 0.f; }

    const int am   = t & 63;
    const int akp0 = t >> 6;
    const int bn   = t >> 2;
    const int boff = t & 3;

    const int nkt = C >> 5;

    // ---- prologue: chunk 0 ----
    {
#pragma unroll
        for (int i = 0; i < 4; i++) {
            const int n = bn + i * 64;
            if (n < 200) {
                const uint32_t dsth = smb + (B_HI_W + n * 20 + boff * 4) * 4;
                const uint32_t dstl = smb + (B_LO_W + n * 20 + boff * 4) * 4;
                asm volatile("cp.async.cg.shared.global [%0], [%1], 16;"
                             :: "r"(dsth), "l"(wh + (size_t)n * C + boff * 8) : "memory");
                asm volatile("cp.async.cg.shared.global [%0], [%1], 16;"
                             :: "r"(dstl), "l"(wl + (size_t)n * C + boff * 8) : "memory");
            }
        }
        asm volatile("cp.async.commit_group;" ::: "memory");
        float v[8];
#pragma unroll
        for (int j = 0; j < 8; j++)
            v[j] = (am < valid) ? xb[(size_t)(akp0 * 8 + j) * HW + am] : 0.f;
        uint32_t hw4[4], lw4[4];
#pragma unroll
        for (int p = 0; p < 4; p++) split2(v[2*p], v[2*p+1], hw4[p], lw4[p]);
        *(uint4*)&sm[am * 20 + akp0 * 4]          = *(uint4*)hw4;
        *(uint4*)&sm[A_LO_W + am * 20 + akp0 * 4] = *(uint4*)lw4;
    }

    for (int kt = 0; kt < nkt; kt++) {
        const int st = (kt & 1) ? ST_WORDS : 0;
        asm volatile("cp.async.wait_group 0;" ::: "memory");
        __syncthreads();

        float apre[8];
        const bool pf = (kt + 1 < nkt);
        const int stn = ((kt + 1) & 1) ? ST_WORDS : 0;
        if (pf) {
            const int c1 = (kt + 1) << 5;
#pragma unroll
            for (int i = 0; i < 4; i++) {
                const int n = bn + i * 64;
                if (n < 200) {
                    const uint32_t dsth = smb + (stn + B_HI_W + n * 20 + boff * 4) * 4;
                    const uint32_t dstl = smb + (stn + B_LO_W + n * 20 + boff * 4) * 4;
                    asm volatile("cp.async.cg.shared.global [%0], [%1], 16;"
                                 :: "r"(dsth), "l"(wh + (size_t)n * C + c1 + boff * 8) : "memory");
                    asm volatile("cp.async.cg.shared.global [%0], [%1], 16;"
                                 :: "r"(dstl), "l"(wl + (size_t)n * C + c1 + boff * 8) : "memory");
                }
            }
            asm volatile("cp.async.commit_group;" ::: "memory");
#pragma unroll
            for (int j = 0; j < 8; j++)
                apre[j] = (am < valid) ? xb[(size_t)(c1 + akp0 * 8 + j) * HW + am] : 0.f;
        }

        // ---- compute current chunk ----
#pragma unroll
        for (int k16 = 0; k16 < 2; k16++) {
            uint32_t ah[2][4], al[2][4];
            const uint32_t acol = k16 * 32 + (lane >> 4) * 16;
#pragma unroll
            for (int mt = 0; mt < 2; mt++) {
                const int row = wm * 32 + mt * 16 + (lane & 15);
                const uint32_t ba = smb + (st + row * 20) * 4 + acol;
                ldm_x4(ah[mt], ba);
                ldm_x4(al[mt], ba + A_LO_W * 4);
            }
            const int brow = (lane & 7) + ((lane >> 4) << 3);
            const uint32_t bcol = ((lane >> 3) & 1) * 16 + k16 * 32;
#pragma unroll
            for (int ntp = 0; ntp < 3; ntp++) {
                const int nb = ncol0 + ntp * 16 + brow;
                uint32_t bh[4], bl[4];
                const uint32_t bbp = smb + (st + B_HI_W + nb * 20) * 4 + bcol;
                ldm_x4(bh, bbp);
                ldm_x4(bl, bbp + (B_LO_W - B_HI_W) * 4);
#pragma unroll
                for (int h = 0; h < 2; h++) {
                    const int g = ntp * 2 + h;
                    mma_f16(acc0[g], ah[0], bh[2*h], bh[2*h+1]);
                    mma_f16(acc0[g], ah[0], bl[2*h], bl[2*h+1]);
                    mma_f16(acc0[g], al[0], bh[2*h], bh[2*h+1]);
                    mma_f16(acc1[g], ah[1], bh[2*h], bh[2*h+1]);
                    mma_f16(acc1[g], ah[1], bl[2*h], bl[2*h+1]);
                    mma_f16(acc1[g], al[1], bh[2*h], bh[2*h+1]);
                }
            }
            if (xtra) {
                const int xrow = 96 + (lane & 7);
                const uint32_t xoff = ((lane >> 3) & 1) * 16 + k16 * 32;
                uint32_t bh2[2], bl2[2];
                const uint32_t xba = smb + (st + B_HI_W + xrow * 20) * 4 + xoff;
                ldm_x2(bh2, xba);
                ldm_x2(bl2, xba + (B_LO_W - B_HI_W) * 4);
                mma_f16(accx0, ah[0], bh2[0], bh2[1]);
                mma_f16(accx0, ah[0], bl2[0], bl2[1]);
                mma_f16(accx0, al[0], bh2[0], bh2[1]);
                mma_f16(accx1, ah[1], bh2[0], bh2[1]);
                mma_f16(accx1, ah[1], bl2[0], bl2[1]);
                mma_f16(accx1, al[1], bh2[0], bh2[1]);
            }
        }

        if (pf) {
            uint32_t hw4[4], lw4[4];
#pragma unroll
            for (int p = 0; p < 4; p++) split2(apre[2*p], apre[2*p+1], hw4[p], lw4[p]);
            *(uint4*)&sm[stn + am * 20 + akp0 * 4]          = *(uint4*)hw4;
            *(uint4*)&sm[stn + A_LO_W + am * 20 + akp0 * 4] = *(uint4*)lw4;
        }
    }
    __syncthreads();   // mainloop done; stage smem reused as D tile

    // ---- stage D tile (cols 0..199, stride 201) ----
#pragma unroll
    for (int ntp = 0; ntp < 3; ntp++) {
#pragma unroll
        for (int h = 0; h < 2; h++) {
            const int n = ncol0 + ntp * 16 + h * 8 + (lane & 3) * 2;
            const int g = ntp * 2 + h;
#pragma unroll
            for (int mt = 0; mt < 2; mt++) {
                const int r = wm * 32 + mt * 16 + (lane >> 2);
                const float* c = (mt == 0) ? acc0[g] : acc1[g];
                smf[SM_D + r * 201 + n]           = c[0];
                smf[SM_D + r * 201 + n + 1]       = c[1];
                smf[SM_D + (r + 8) * 201 + n]     = c[2];
                smf[SM_D + (r + 8) * 201 + n + 1] = c[3];
            }
        }
    }
    if (xtra) {
        const int n = 96 + (lane & 3) * 2;
#pragma unroll
        for (int mt = 0; mt < 2; mt++) {
            const int r = wm * 32 + mt * 16 + (lane >> 2);
            const float* c = (mt == 0) ? accx0 : accx1;
            smf[SM_D + r * 201 + n]           = c[0];
            smf[SM_D + r * 201 + n + 1]       = c[1];
            smf[SM_D + (r + 8) * 201 + n]     = c[2];
            smf[SM_D + (r + 8) * 201 + n + 1] = c[3];
        }
    }
    __syncthreads();

    // ---- decode epilogue: 4 threads per anchor (64 x 4 = 256) ----
    {
        const int ar  = t >> 2;
        const int sub = t & 3;
        const bool ok = ar < valid;
        const int pos = pos0 + ar;
        const int a_g = soffA[s] + pos;
        const int py = pos / W, px = pos - py * W;
        const float gx = px + 0.5f, gy = py + 0.5f;
        const float* Dr = smf + SM_D + ar * 201;
        const float* bi = smf + SM_BIAS;
        const unsigned msk = 0xffffffffu;

        float v16[16];
#pragma unroll
        for (int i = 0; i < 16; i++) v16[i] = Dr[sub * 16 + i] + bi[sub * 16 + i];
        float d = dfl16(v16);
        const float d0 = __shfl_sync(msk, d, 0, 4);
        const float d1 = __shfl_sync(msk, d, 1, 4);
        const float d2 = __shfl_sync(msk, d, 2, 4);
        const float d3 = __shfl_sync(msk, d, 3, 4);
        if (ok && sub == 0) {
            float x1 = gx - d0, y1 = gy - d1;
            float x2 = gx + d2, y2 = gy + d3;
            g_dbox[((size_t)b * 4 + 0) * A_TOT + a_g] = (x1 + x2) * 0.5f * stride;
            g_dbox[((size_t)b * 4 + 1) * A_TOT + a_g] = (y1 + y2) * 0.5f * stride;
            g_dbox[((size_t)b * 4 + 2) * A_TOT + a_g] = (x2 - x1) * stride;
            g_dbox[((size_t)b * 4 + 3) * A_TOT + a_g] = (y2 - y1) * stride;
        }

        float best = -INFINITY; int bcls = 0;
#pragma unroll
        for (int c = 0; c < 20; c++) {
            const int cc = sub * 20 + c;
            float v = Dr[64 + cc] + bi[64 + cc];
            if (v > best) { best = v; bcls = cc; }
        }
#pragma unroll
        for (int o = 2; o > 0; o >>= 1) {
            float v2 = __shfl_down_sync(msk, best, o, 4);
            int   i2 = __shfl_down_sync(msk, bcls, o, 4);
            if (v2 > best || (v2 == best && i2 < bcls)) { best = v2; bcls = i2; }
        }
        if (ok && sub == 0) {
            g_maxs[b * A_TOT + a_g] = 1.f / (1.f + expf(-best));
            g_cls[b * A_TOT + a_g]  = bcls;
        }

        if (ok) {
            for (int nk = sub; nk < NKPT; nk += 4) {
                float v = Dr[144 + nk] + bi[144 + nk];
                const int comp = nk % 3;
                float o = (comp == 0) ? (v * 2.f + (gx - 0.5f)) * stride
                        : (comp == 1) ? (v * 2.f + (gy - 0.5f)) * stride
                                      : 1.f / (1.f + expf(-v));
                g_kpts[((size_t)b * NKPT + nk) * A_TOT + a_g] = o;
            }
        }
    }
}

// ---------------------------------------------------------------------------
// Per-batch top-100 via histogram threshold + bitonic sort of candidates.
// ---------------------------------------------------------------------------
#define NBIN 4096
#define CANDC 1024

__global__ void __launch_bounds__(1024) topk_k(float* __restrict__ out)
{
    __shared__ int hist[NBIN];
    __shared__ int coarse[256];
    __shared__ unsigned long long cand[CANDC];
    __shared__ int s_cnt, s_T;
    __shared__ int s_idx[MAX_DET];
    __shared__ float s_val[MAX_DET];

    const int b = blockIdx.x;
    const int t = threadIdx.x;
    const float* scores = g_maxs + b * A_TOT;

#pragma unroll
    for (int i = 0; i < NBIN / 1024; i++) hist[t + i * 1024] = 0;
    if (t < CANDC) cand[t] = 0ull;
    if (t == 0) s_cnt = 0;
    __syncthreads();

    for (int i = t; i < A_TOT; i += 1024) {
        int bin = min(NBIN - 1, max(0, (int)(scores[i] * (float)NBIN)));
        atomicAdd(&hist[bin], 1);
    }
    __syncthreads();

    if (t < 256) {
        int sum = 0;
#pragma unroll
        for (int i = 0; i < 16; i++) sum += hist[t * 16 + i];
        coarse[t] = sum;
    }
    __syncthreads();

    if (t == 0) {
        int acc = 0, T = 0;
        int c;
        for (c = 255; c >= 0; c--) {
            if (acc + coarse[c] >= MAX_DET) break;
            acc += coarse[c];
        }
        if (c < 0) { T = 0; }
        else {
            for (int bin = c * 16 + 15; bin >= c * 16; bin--) {
                acc += hist[bin];
                if (acc >= MAX_DET) { T = bin; break; }
                if (bin == c * 16) T = bin;
            }
        }
        s_T = T;
    }
    __syncthreads();

    const int T = s_T;
    for (int i = t; i < A_TOT; i += 1024) {
        float v = scores[i];
        int bin = min(NBIN - 1, max(0, (int)(v * (float)NBIN)));
        if (bin >= T) {
            int pos = atomicAdd(&s_cnt, 1);
            if (pos < CANDC)
                cand[pos] = ((unsigned long long)__float_as_uint(v) << 32)
                          | (unsigned long long)(A_TOT - 1 - i);
        }
    }
    __syncthreads();

    for (int k = 2; k <= CANDC; k <<= 1) {
        for (int j = k >> 1; j > 0; j >>= 1) {
            if (t < CANDC / 2) {
                int idx = ((t & ~(j - 1)) << 1) | (t & (j - 1));
                int ixj = idx | j;
                unsigned long long a = cand[idx], bb2 = cand[ixj];
                bool descBlk = ((idx & k) == 0);
                if ((a < bb2) == descBlk) { cand[idx] = bb2; cand[ixj] = a; }
            }
            __syncthreads();
        }
    }

    if (t < MAX_DET) {
        unsigned long long key = cand[t];
        s_val[t] = __uint_as_float((uint32_t)(key >> 32));
        s_idx[t] = A_TOT - 1 - (int)(key & 0xFFFFFFFFull);
    }
    __syncthreads();

    if (t == 0) {
        int cnt = 0;
        for (int j = 0; j < MAX_DET; j++) cnt += (s_val[j] > CONF) ? 1 : 0;
        out[O_NUM + b] = (float)cnt;
    }
    for (int e = t; e < MAX_DET * 4; e += 1024) {
        int j = e >> 2, c = e & 3;
        out[O_BOX + ((size_t)b * MAX_DET + j) * 4 + c] =
            g_dbox[((size_t)b * 4 + c) * A_TOT + s_idx[j]];
    }
    for (int j = t; j < MAX_DET; j += 1024) {
        out[O_SCORE + b * MAX_DET + j] = s_val[j];
        out[O_CLS   + b * MAX_DET + j] = (float)g_cls[b * A_TOT + s_idx[j]];
    }
    for (int e = t; e < MAX_DET * NKPT; e += 1024) {
        int j = e / NKPT, nk = e - j * NKPT;
        out[O_KPT + ((size_t)b * MAX_DET + j) * NKPT + nk] =
            g_kpts[((size_t)b * NKPT + nk) * A_TOT + s_idx[j]];
    }
}

// ---------------------------------------------------------------------------
extern "C" void kernel_launch(void* const* d_in, const int* in_sizes, int n_in,
                              void* d_out, int out_size)
{
    cudaFuncSetAttribute(gemm_tc, cudaFuncAttributeMaxDynamicSharedMemorySize, SMEM_BYTES);

    pack_k<<<(57344 + 255) / 256, 256>>>(
        (const float*)d_in[3],  (const float*)d_in[4],
        (const float*)d_in[5],  (const float*)d_in[6],
        (const float*)d_in[7],  (const float*)d_in[8],
        (const float*)d_in[9],  (const float*)d_in[10],
        (const float*)d_in[11], (const float*)d_in[12],
        (const float*)d_in[13], (const float*)d_in[14],
        (const float*)d_in[15], (const float*)d_in[16],
        (const float*)d_in[17], (const float*)d_in[18],
        (const float*)d_in[19], (const float*)d_in[20]);

    gemm_tc<<<2112, 256, SMEM_BYTES>>>((const float*)d_in[0],
                                       (const float*)d_in[1],
                                       (const float*)d_in[2]);

    topk_k<<<BS, 1024>>>((float*)d_out);
}